// round 4
// baseline (speedup 1.0000x reference)
#include <cuda_runtime.h>
#include <cuda_bf16.h>

#define HIDDEN 2048
#define INTER  1408
#define TOP_K  4
#define NROWS  (TOP_K * INTER)          // 5632 gate/up row-pairs, == g_inter size
#define NCHUNK 44                        // 5632 / 128: ready-flag granularity
#define GRID   148                       // one block per SM -> all co-resident
#define WPB    16                        // warps per block (512 threads)
#define TOTAL_WARPS (GRID * WPB)         // 2368

// Weighted intermediate activations, linear index r = e*INTER + i
__device__ float g_inter[NROWS];
// Per-chunk completion counters (chunk c = rows [128c, 128c+128))
__device__ int g_ctr[NCHUNK];

__global__ void reset_kernel() {
    if (threadIdx.x < NCHUNK) g_ctr[threadIdx.x] = 0;
}

__device__ __forceinline__ int ld_acquire(const int* p) {
    int v;
    asm volatile("ld.acquire.gpu.global.b32 %0, [%1];" : "=r"(v) : "l"(p) : "memory");
    return v;
}

// ---------------------------------------------------------------------------
// Fused persistent MoE kernel.
// Phase 1 (producer): warp gw computes gate/up dot for rows r = gw, gw+2368,
//   gw+4736; writes g_inter[r] = topk_w * silu(g) * u; bumps chunk counter.
// Phase 2 (consumer): warp gw (< 2048) computes out[h=gw] =
//   sum_c dot(down[ex(c)][h][chunk c], g_inter[chunk c]) over 44 chunks,
//   spin-waiting on chunk readiness. Down DRAM stream overlaps other warps'
//   gate/up DRAM stream.
// ---------------------------------------------------------------------------
__global__ __launch_bounds__(512)
void moe_fused_kernel(const float* __restrict__ x,
                      const int*   __restrict__ topk_idx,
                      const float* __restrict__ topk_w,
                      const float* __restrict__ gate_all,
                      const float* __restrict__ up_all,
                      const float* __restrict__ down_all,
                      float*       __restrict__ out)
{
    __shared__ float4 x_s[HIDDEN / 4];   // 8 KB

    const int tid  = threadIdx.x;
    const int lane = tid & 31;
    const int warp = tid >> 5;
    const int gw   = blockIdx.x * WPB + warp;

    // Stage x: 512 float4 / 512 threads
    x_s[tid] = reinterpret_cast<const float4*>(x)[tid];
    __syncthreads();

    // ---------------- Phase 1: gate/up producer ----------------
    for (int r = gw; r < NROWS; r += TOTAL_WARPS) {
        const int e = r / INTER;
        const int i = r - e * INTER;
        const long long ex = topk_idx[e];
        const long long base = (ex * INTER + i) * (long long)HIDDEN;
        const float4* g4 = reinterpret_cast<const float4*>(gate_all + base);
        const float4* u4 = reinterpret_cast<const float4*>(up_all   + base);

        float gacc = 0.f, uacc = 0.f;
#pragma unroll
        for (int j = 0; j < 16; j++) {
            const int idx = j * 32 + lane;
            const float4 xv = x_s[idx];
            const float4 gv = __ldcs(g4 + idx);   // streaming, evict-first
            const float4 uv = __ldcs(u4 + idx);
            gacc += gv.x * xv.x + gv.y * xv.y + gv.z * xv.z + gv.w * xv.w;
            uacc += uv.x * xv.x + uv.y * xv.y + uv.z * xv.z + uv.w * xv.w;
        }
#pragma unroll
        for (int off = 16; off > 0; off >>= 1) {
            gacc += __shfl_xor_sync(0xFFFFFFFFu, gacc, off);
            uacc += __shfl_xor_sync(0xFFFFFFFFu, uacc, off);
        }
        if (lane == 0) {
            const float w = topk_w[e];
            const float silu = gacc / (1.0f + __expf(-gacc));
            g_inter[r] = w * silu * uacc;
            __threadfence();                       // publish g_inter[r]
            atomicAdd(&g_ctr[r >> 7], 1);          // then signal chunk
        }
    }

    // ---------------- Phase 2: down consumer ----------------
    const int h = gw;
    if (h >= HIDDEN) return;

    const float4* dptr[TOP_K];
#pragma unroll
    for (int e = 0; e < TOP_K; e++) {
        const long long ex = topk_idx[e];
        dptr[e] = reinterpret_cast<const float4*>(
            down_all + (ex * HIDDEN + h) * (long long)INTER);
    }
    const float4* gi4 = reinterpret_cast<const float4*>(g_inter);

    float acc = 0.f;
#pragma unroll 1
    for (int grp = 0; grp < 11; grp++) {
        const int cbase = grp * 4;
        // Wait until all 4 chunks of this group are published (128 rows each).
#pragma unroll
        for (int k = 0; k < 4; k++) {
            while (ld_acquire(&g_ctr[cbase + k]) < 128) { }
        }
        // Each lane consumes one float4 per chunk (4*32*4 = 512 floats/group).
#pragma unroll
        for (int k = 0; k < 4; k++) {
            const int c  = cbase + k;
            const int e  = c / 11;          // expert-major chunk order
            const int ib = c - e * 11;      // i-block within expert
            const float4 dv = __ldcs(dptr[e] + ib * 32 + lane);
            const float4 gv = gi4[c * 32 + lane];
            acc += dv.x * gv.x + dv.y * gv.y + dv.z * gv.z + dv.w * gv.w;
        }
    }

#pragma unroll
    for (int off = 16; off > 0; off >>= 1)
        acc += __shfl_xor_sync(0xFFFFFFFFu, acc, off);

    if (lane == 0)
        out[h] = acc;
}

extern "C" void kernel_launch(void* const* d_in, const int* in_sizes, int n_in,
                              void* d_out, int out_size)
{
    const float* x        = (const float*)d_in[0];   // (1, 2048, 1, 1)
    const int*   topk_idx = (const int*)  d_in[1];   // (4,)
    const float* topk_w   = (const float*)d_in[2];   // (4,)
    const float* gate_all = (const float*)d_in[3];   // (60, 1408, 2048)
    const float* up_all   = (const float*)d_in[4];   // (60, 1408, 2048)
    const float* down_all = (const float*)d_in[5];   // (60, 2048, 1408)
    float* out = (float*)d_out;                      // (1, 2048, 1, 1)

    reset_kernel<<<1, 64>>>();
    moe_fused_kernel<<<GRID, 512>>>(x, topk_idx, topk_w,
                                    gate_all, up_all, down_all, out);
}

// round 5
// speedup vs baseline: 2.3477x; 2.3477x over previous
#include <cuda_runtime.h>
#include <cuda_bf16.h>

#define HIDDEN 2048
#define INTER  1408
#define TOP_K  4

// Scratch for weighted intermediate activations: topk_w[e] * silu(gate)*up
__device__ float g_inter[TOP_K * INTER];

// ---------------------------------------------------------------------------
// Kernel 1: gate/up GEMV + SiLU, with embedded L2 prefetch of the down
// matrices. Block (bx, e) additionally prefetches bytes
// [bx*65536, (bx+1)*65536) of down[topk_idx[e]] into L2 (176 blocks x 64 KB
// = 11.53 MB per expert, exact). 2 prefetch instrs per thread (~8 cyc) —
// the 46 MB down fetch streams concurrently with the 92 MB gate/up stream.
// grid: (176, 4), block: 256 threads (8 warps, 1 row per warp)
// ---------------------------------------------------------------------------
__global__ __launch_bounds__(256)
void moe_gate_up_kernel(const float* __restrict__ x,
                        const int*   __restrict__ topk_idx,
                        const float* __restrict__ topk_w,
                        const float* __restrict__ gate_all,
                        const float* __restrict__ up_all,
                        const float* __restrict__ down_all)
{
    __shared__ float4 x_s[HIDDEN / 4];   // 8 KB

    const int tid  = threadIdx.x;
    const int lane = tid & 31;
    const int warp = tid >> 5;
    const int e    = blockIdx.y;                // expert slot 0..3
    const long long ex = topk_idx[e];

    // --- Embedded prefetch of this expert's down block slice (fire & forget)
    {
        const char* dbase = reinterpret_cast<const char*>(
            down_all + ex * (long long)(HIDDEN * INTER));
        const long long off = (long long)blockIdx.x * 65536 + tid * 128;
        asm volatile("prefetch.global.L2 [%0];" :: "l"(dbase + off));
        asm volatile("prefetch.global.L2 [%0];" :: "l"(dbase + off + 32768));
    }

    // Stage x into shared memory: 512 float4 / 256 threads = 2 each
    const float4* x4 = reinterpret_cast<const float4*>(x);
    x_s[tid]       = x4[tid];
    x_s[tid + 256] = x4[tid + 256];
    __syncthreads();

    const int row = blockIdx.x * 8 + warp;      // 0..1407

    const float4* g4 = reinterpret_cast<const float4*>(
        gate_all + (ex * INTER + row) * (long long)HIDDEN);
    const float4* u4 = reinterpret_cast<const float4*>(
        up_all   + (ex * INTER + row) * (long long)HIDDEN);

    float gacc = 0.f, uacc = 0.f;
    // 512 float4 per row, 32 lanes -> 16 iterations
#pragma unroll
    for (int j = 0; j < 16; j++) {
        const int idx = j * 32 + lane;
        const float4 xv = x_s[idx];
        const float4 gv = __ldcs(g4 + idx);   // streaming: evict-first
        const float4 uv = __ldcs(u4 + idx);
        gacc += gv.x * xv.x + gv.y * xv.y + gv.z * xv.z + gv.w * xv.w;
        uacc += uv.x * xv.x + uv.y * xv.y + uv.z * xv.z + uv.w * xv.w;
    }

    // warp reduce
#pragma unroll
    for (int off = 16; off > 0; off >>= 1) {
        gacc += __shfl_xor_sync(0xFFFFFFFFu, gacc, off);
        uacc += __shfl_xor_sync(0xFFFFFFFFu, uacc, off);
    }

    if (lane == 0) {
        const float w = topk_w[e];
        const float silu = gacc / (1.0f + __expf(-gacc));
        g_inter[e * INTER + row] = w * silu * uacc;
    }
}

// ---------------------------------------------------------------------------
// Kernel 2: out[h] = sum_e dot(down[ex_e][h][:], g_inter[e][:])
// Warp per h over an expert PAIR (grid.y selects the pair): down reads hit
// L2 thanks to the prefetch embedded in kernel 1. Pairs combined via
// atomicAdd (2 commutative adds per h). out zeroed by cudaMemsetAsync.
// grid: (256, 2), block: 256 threads (8 warps, 1 h per warp)
// ---------------------------------------------------------------------------
__global__ __launch_bounds__(256)
void moe_down_kernel(const int*   __restrict__ topk_idx,
                     const float* __restrict__ down_all,
                     float*       __restrict__ out)
{
    __shared__ float4 gi_s[2 * INTER / 4];   // 704 float4 = 11.25 KB

    const int tid  = threadIdx.x;
    const int lane = tid & 31;
    const int warp = tid >> 5;
    const int p    = blockIdx.y;             // expert pair 0..1

    // Stage g_inter for experts 2p, 2p+1
    const float4* gi4 = reinterpret_cast<const float4*>(g_inter + 2 * p * INTER);
    for (int k = tid; k < 704; k += 256)
        gi_s[k] = gi4[k];
    __syncthreads();

    const int h = blockIdx.x * 8 + warp;     // 0..2047

    const long long e0 = topk_idx[2 * p];
    const long long e1 = topk_idx[2 * p + 1];
    const float4* d0 = reinterpret_cast<const float4*>(
        down_all + (e0 * HIDDEN + h) * (long long)INTER);
    const float4* d1 = reinterpret_cast<const float4*>(
        down_all + (e1 * HIDDEN + h) * (long long)INTER);

    float acc0 = 0.f, acc1 = 0.f;
    // 352 float4 per expert row, 32 lanes -> 11 iterations, 2 experts
#pragma unroll
    for (int j = 0; j < 11; j++) {
        const int idx = j * 32 + lane;
        const float4 a0 = __ldg(d0 + idx);
        const float4 a1 = __ldg(d1 + idx);
        const float4 v0 = gi_s[idx];
        const float4 v1 = gi_s[idx + 352];
        acc0 += a0.x * v0.x + a0.y * v0.y + a0.z * v0.z + a0.w * v0.w;
        acc1 += a1.x * v1.x + a1.y * v1.y + a1.z * v1.z + a1.w * v1.w;
    }

    float acc = acc0 + acc1;
#pragma unroll
    for (int off = 16; off > 0; off >>= 1)
        acc += __shfl_xor_sync(0xFFFFFFFFu, acc, off);

    if (lane == 0)
        atomicAdd(&out[h], acc);
}

extern "C" void kernel_launch(void* const* d_in, const int* in_sizes, int n_in,
                              void* d_out, int out_size)
{
    const float* x        = (const float*)d_in[0];   // (1, 2048, 1, 1)
    const int*   topk_idx = (const int*)  d_in[1];   // (4,)
    const float* topk_w   = (const float*)d_in[2];   // (4,)
    const float* gate_all = (const float*)d_in[3];   // (60, 1408, 2048)
    const float* up_all   = (const float*)d_in[4];   // (60, 1408, 2048)
    const float* down_all = (const float*)d_in[5];   // (60, 2048, 1408)
    float* out = (float*)d_out;                      // (1, 2048, 1, 1)

    cudaMemsetAsync(out, 0, HIDDEN * sizeof(float));

    dim3 grid1(INTER / 8, TOP_K);
    moe_gate_up_kernel<<<grid1, 256>>>(x, topk_idx, topk_w,
                                       gate_all, up_all, down_all);

    moe_down_kernel<<<dim3(HIDDEN / 8, 2), 256>>>(topk_idx, down_all, out);
}